// round 10
// baseline (speedup 1.0000x reference)
#include <cuda_runtime.h>
#include <cuda_bf16.h>
#include <cuda_fp8.h>
#include <math.h>
#include <stdint.h>

// ---------------------------------------------------------------------------
// Problem constants
// ---------------------------------------------------------------------------
#define SEQ     4096
#define HIDDEN  1024
#define BATCH   2
#define MROWS   (BATCH * SEQ)   // 8192
#define MH      (MROWS * HIDDEN)

// GEMM operands
__device__ __nv_bfloat16 g_Xhi[MH];                 // bf16(x)
__device__ uint8_t       g_X8[MH];                  // e4m3(x)
__device__ uint8_t       g_Xl8[MH];                 // e4m3((x - bf16(x)) * 2^9)
__device__ __nv_bfloat16 g_Whi[3 * HIDDEN * HIDDEN];// bf16(w), [proj*1024+n][k]
__device__ uint8_t       g_W8[3 * HIDDEN * HIDDEN]; // e4m3(w * 2^6)
__device__ uint8_t       g_Wl8[3 * HIDDEN * HIDDEN];// e4m3((w - bf16(w)) * 2^15)
// Projection outputs as bf16 hi/lo: [proj][m 8192][col 1024] (col = head*64+d)
__device__ __nv_bfloat16 g_Ohi[3 * MH];
__device__ __nv_bfloat16 g_Olo[3 * MH];

// ---------------------------------------------------------------------------
// PTX helpers
// ---------------------------------------------------------------------------
__device__ __forceinline__ uint32_t smem_u32(const void* p) {
    uint32_t a;
    asm("{ .reg .u64 t; cvta.to.shared.u64 t, %1; cvt.u32.u64 %0, t; }" : "=r"(a) : "l"(p));
    return a;
}
#define CP_ASYNC16(dst, src) \
    asm volatile("cp.async.cg.shared.global [%0], [%1], 16;" :: "r"(dst), "l"(src) : "memory")
#define CP_COMMIT() asm volatile("cp.async.commit_group;" ::: "memory")
#define CP_WAIT2()  asm volatile("cp.async.wait_group 2;" ::: "memory")
#define CP_WAIT1()  asm volatile("cp.async.wait_group 1;" ::: "memory")
#define CP_WAIT0()  asm volatile("cp.async.wait_group 0;" ::: "memory")

__device__ __forceinline__ void ldsm_x4(uint32_t* r, uint32_t addr) {
    asm volatile("ldmatrix.sync.aligned.m8n8.x4.shared.b16 {%0,%1,%2,%3}, [%4];"
                 : "=r"(r[0]), "=r"(r[1]), "=r"(r[2]), "=r"(r[3]) : "r"(addr));
}
__device__ __forceinline__ void ldsm_x4_t(uint32_t* r, uint32_t addr) {
    asm volatile("ldmatrix.sync.aligned.m8n8.x4.trans.shared.b16 {%0,%1,%2,%3}, [%4];"
                 : "=r"(r[0]), "=r"(r[1]), "=r"(r[2]), "=r"(r[3]) : "r"(addr));
}
__device__ __forceinline__ void mma_bf16(float* c, const uint32_t* a, const uint32_t* b) {
    asm volatile("mma.sync.aligned.m16n8k16.row.col.f32.bf16.bf16.f32 "
                 "{%0,%1,%2,%3}, {%4,%5,%6,%7}, {%8,%9}, {%0,%1,%2,%3};"
                 : "+f"(c[0]), "+f"(c[1]), "+f"(c[2]), "+f"(c[3])
                 : "r"(a[0]), "r"(a[1]), "r"(a[2]), "r"(a[3]), "r"(b[0]), "r"(b[1]));
}
__device__ __forceinline__ void mma_fp8(float* c, const uint32_t* a, const uint32_t* b) {
    asm volatile("mma.sync.aligned.m16n8k32.row.col.f32.e4m3.e4m3.f32 "
                 "{%0,%1,%2,%3}, {%4,%5,%6,%7}, {%8,%9}, {%0,%1,%2,%3};"
                 : "+f"(c[0]), "+f"(c[1]), "+f"(c[2]), "+f"(c[3])
                 : "r"(a[0]), "r"(a[1]), "r"(a[2]), "r"(a[3]), "r"(b[0]), "r"(b[1]));
}
// Fast exp on the FMA pipe. |rel err| < 3e-6 for t in [-80, 0].
__device__ __forceinline__ float fast_exp(float t) {
    float y = t * 1.442695041f;
    float z = y + 12582912.0f;
    float n = z - 12582912.0f;
    float f = y - n;
    float p =            1.33336e-3f;
    p = fmaf(p, f,       9.61815e-3f);
    p = fmaf(p, f,       5.55042e-2f);
    p = fmaf(p, f,       2.40226e-1f);
    p = fmaf(p, f,       6.93147e-1f);
    p = fmaf(p, f,       1.0f);
    int e = __float2int_rn(n);
    float s = __int_as_float((e + 127) << 23);
    return s * p;
}
__device__ __forceinline__ uint32_t pack_bf16(float a, float b) {
    __nv_bfloat162 h = __floats2bfloat162_rn(a, b);
    return *(uint32_t*)&h;
}
__device__ __forceinline__ uint8_t to_e4m3(float v) {
    return (uint8_t)__nv_cvt_float_to_fp8(v, __NV_SATFINITE, __NV_E4M3);
}

// ---------------------------------------------------------------------------
// X -> bf16 hi + e4m3(x) + e4m3(xl * 2^9)
// ---------------------------------------------------------------------------
__global__ __launch_bounds__(256) void cvt_x(const float* __restrict__ X) {
    int i = blockIdx.x * 256 + threadIdx.x;          // float4 index
    float4 v = ((const float4*)X)[i];
    float f[4] = {v.x, v.y, v.z, v.w};
    __nv_bfloat16 h[4];
    uint32_t x8 = 0, xl8 = 0;
    #pragma unroll
    for (int j = 0; j < 4; j++) {
        h[j] = __float2bfloat16(f[j]);
        float l = f[j] - __bfloat162float(h[j]);
        x8  |= (uint32_t)to_e4m3(f[j]) << (j * 8);
        xl8 |= (uint32_t)to_e4m3(l * 512.0f) << (j * 8);
    }
    ((__nv_bfloat162*)g_Xhi)[2 * i]     = __halves2bfloat162(h[0], h[1]);
    ((__nv_bfloat162*)g_Xhi)[2 * i + 1] = __halves2bfloat162(h[2], h[3]);
    ((uint32_t*)g_X8)[i]  = x8;
    ((uint32_t*)g_Xl8)[i] = xl8;
}

// ---------------------------------------------------------------------------
// W [k][n] fp32 -> [proj*1024+n][k]: bf16 hi + e4m3(w*2^6) + e4m3(wl*2^15)
// ---------------------------------------------------------------------------
__global__ void cvt_w(const float* __restrict__ Wq,
                      const float* __restrict__ Wk,
                      const float* __restrict__ Wv) {
    __shared__ float s[32][33];
    const int proj = blockIdx.z;
    const float* W = proj == 0 ? Wq : (proj == 1 ? Wk : Wv);
    const int k0 = blockIdx.x * 32, n0 = blockIdx.y * 32;
    const int tx = threadIdx.x, ty = threadIdx.y;
    #pragma unroll
    for (int j = 0; j < 32; j += 8)
        s[ty + j][tx] = W[(k0 + ty + j) * 1024 + n0 + tx];
    __syncthreads();
    #pragma unroll
    for (int j = 0; j < 32; j += 8) {
        float v = s[tx][ty + j];
        int n = n0 + ty + j, k = k0 + tx;
        __nv_bfloat16 hi = __float2bfloat16(v);
        float lo = v - __bfloat162float(hi);
        size_t o = ((size_t)proj * 1024 + n) * 1024 + k;
        g_Whi[o] = hi;
        g_W8[o]  = to_e4m3(v * 64.0f);
        g_Wl8[o] = to_e4m3(lo * 32768.0f);
    }
}

// ---------------------------------------------------------------------------
// Projection GEMM: main term bf16 mma, cross terms via one fp8 accumulator.
//   C     = sum xh*wh                              (bf16 m16n8k16)
//   Ccorr = sum x*(wl*2^15) + (xl*2^9)*(w*2^6)     (e4m3 m16n8k32, scale 2^15)
//   out   = C + Ccorr*2^-15 + bias
// CTA 128x128, 8 warps (4m x 2n), K chunks of 32, 4-stage cp.async.
// ---------------------------------------------------------------------------
#define PITCHB   80                       // bf16 rows: 32 halves (64B) @80B
#define PITCH8   48                       // fp8 rows: 32 bytes @48B
#define S_AHI    0
#define S_BHI    10240
#define S_X8     20480
#define S_XL8    26624
#define S_WL8    32768
#define S_W8     38912
#define STAGE_BYTES 45056
#define NSTAGE   4
#define GEMM_SMEM (NSTAGE * STAGE_BYTES)  // 180224

__global__ __launch_bounds__(256) void qkv_gemm_mma(
    const float* __restrict__ Bq, const float* __restrict__ Bk,
    const float* __restrict__ Bv) {
    extern __shared__ __align__(128) char smem[];
    const uint32_t sb = smem_u32(smem);
    const int t = threadIdx.x, lane = t & 31, wid = t >> 5;
    const int warp_m = wid >> 1, warp_n = wid & 1;
    const int m0 = blockIdx.y * 128;
    const int n0g = blockIdx.x * 128;
    const int proj = n0g >> 10;
    const int col0 = n0g & 1023;
    const float* Bias = proj == 0 ? Bq : (proj == 1 ? Bk : Bv);
    __nv_bfloat16* OutHi = g_Ohi + (size_t)proj * MH;
    __nv_bfloat16* OutLo = g_Olo + (size_t)proj * MH;

    __shared__ float sbias[128];
    if (t < 128) sbias[t] = Bias[col0 + t];

    const int lrow = t >> 1;
    const __nv_bfloat16* gAh = g_Xhi + (size_t)(m0 + lrow) * 1024;
    const __nv_bfloat16* gBh = g_Whi + (size_t)(n0g + lrow) * 1024;
    const uint8_t* gX8  = g_X8  + (size_t)(m0 + lrow) * 1024;
    const uint8_t* gXl8 = g_Xl8 + (size_t)(m0 + lrow) * 1024;
    const uint8_t* gW8  = g_W8  + (size_t)(n0g + lrow) * 1024;
    const uint8_t* gWl8 = g_Wl8 + (size_t)(n0g + lrow) * 1024;

    auto load_chunk = [&](int slot, int kc) {
        uint32_t base = sb + slot * STAGE_BYTES;
        // bf16 rows are 64 bytes = 4x16B; this thread handles 2 chunks
        #pragma unroll
        for (int c2 = 0; c2 < 2; c2++) {
            int c = (t & 1) * 2 + c2;                // 16B chunk 0..3
            CP_ASYNC16(base + S_AHI + lrow * PITCHB + c * 16, gAh + kc + c * 8);
            CP_ASYNC16(base + S_BHI + lrow * PITCHB + c * 16, gBh + kc + c * 8);
        }
        // fp8 rows are 32 bytes = 2x16B; this thread handles 1 chunk each
        {
            int c = t & 1;
            uint32_t off = lrow * PITCH8 + c * 16;
            int go = kc + c * 16;
            CP_ASYNC16(base + S_X8  + off, gX8  + go);
            CP_ASYNC16(base + S_XL8 + off, gXl8 + go);
            CP_ASYNC16(base + S_WL8 + off, gWl8 + go);
            CP_ASYNC16(base + S_W8  + off, gW8  + go);
        }
    };

    float C[2][8][4], Cc[2][8][4];
    #pragma unroll
    for (int mt = 0; mt < 2; mt++)
        #pragma unroll
        for (int nt = 0; nt < 8; nt++)
            #pragma unroll
            for (int j = 0; j < 4; j++) { C[mt][nt][j] = 0.0f; Cc[mt][nt][j] = 0.0f; }

    load_chunk(0, 0);  CP_COMMIT();
    load_chunk(1, 32); CP_COMMIT();
    load_chunk(2, 64); CP_COMMIT();

    const int a_r   = warp_m * 32 + (lane & 15);     // +mt*16
    const int b_r   = warp_n * 64 + ((lane >> 4) << 3) + (lane & 7);  // +p*16
    const int b_csel = (lane >> 3) & 1;

    for (int ch = 0; ch < 32; ch++) {
        if (ch <= 29)      CP_WAIT2();
        else if (ch == 30) CP_WAIT1();
        else               CP_WAIT0();
        __syncthreads();

        if (ch + 3 < 32) {
            load_chunk((ch + 3) & (NSTAGE - 1), (ch + 3) * 32);
            CP_COMMIT();
        }

        const uint32_t base = sb + (ch & (NSTAGE - 1)) * STAGE_BYTES;

        // ---- fp8 corrections: one k32 step covers the whole chunk ----
        {
            uint32_t a8x[2][4], a8l[2][4];
            #pragma unroll
            for (int mt = 0; mt < 2; mt++) {
                uint32_t ra = base + (uint32_t)(a_r + mt * 16) * PITCH8
                            + (uint32_t)(lane >> 4) * 16;
                ldsm_x4(a8x[mt], ra + S_X8);
                ldsm_x4(a8l[mt], ra + S_XL8);
            }
            uint32_t bwl[8][2], bw[8][2];
            #pragma unroll
            for (int p = 0; p < 4; p++) {
                uint32_t rb = base + (uint32_t)(b_r + p * 16) * PITCH8
                            + (uint32_t)b_csel * 16;
                uint32_t rr[4];
                ldsm_x4(rr, rb + S_WL8);
                bwl[p * 2][0] = rr[0]; bwl[p * 2][1] = rr[1];
                bwl[p * 2 + 1][0] = rr[2]; bwl[p * 2 + 1][1] = rr[3];
                ldsm_x4(rr, rb + S_W8);
                bw[p * 2][0] = rr[0]; bw[p * 2][1] = rr[1];
                bw[p * 2 + 1][0] = rr[2]; bw[p * 2 + 1][1] = rr[3];
            }
            #pragma unroll
            for (int mt = 0; mt < 2; mt++)
                #pragma unroll
                for (int nt = 0; nt < 8; nt++) {
                    mma_fp8(Cc[mt][nt], a8x[mt], bwl[nt]);
                    mma_fp8(Cc[mt][nt], a8l[mt], bw[nt]);
                }
        }

        // ---- bf16 main term: 2 k16 steps ----
        #pragma unroll
        for (int ks = 0; ks < 2; ks++) {
            uint32_t a_hi[2][4];
            #pragma unroll
            for (int mt = 0; mt < 2; mt++) {
                uint32_t ra = base + S_AHI + (uint32_t)(a_r + mt * 16) * PITCHB
                            + (uint32_t)(lane >> 4) * 16 + ks * 32;
                ldsm_x4(a_hi[mt], ra);
            }
            uint32_t b_hi[8][2];
            #pragma unroll
            for (int p = 0; p < 4; p++) {
                uint32_t rb = base + S_BHI + (uint32_t)(b_r + p * 16) * PITCHB
                            + (uint32_t)b_csel * 16 + ks * 32;
                uint32_t rr[4];
                ldsm_x4(rr, rb);
                b_hi[p * 2][0] = rr[0]; b_hi[p * 2][1] = rr[1];
                b_hi[p * 2 + 1][0] = rr[2]; b_hi[p * 2 + 1][1] = rr[3];
            }
            #pragma unroll
            for (int mt = 0; mt < 2; mt++)
                #pragma unroll
                for (int nt = 0; nt < 8; nt++)
                    mma_bf16(C[mt][nt], a_hi[mt], b_hi[nt]);
        }
    }

    // epilogue: combine, bias, split to bf16 hi/lo
    const float CS = 1.0f / 32768.0f;
    #pragma unroll
    for (int mt = 0; mt < 2; mt++) {
        const int row0 = m0 + warp_m * 32 + mt * 16 + (lane >> 2);
        #pragma unroll
        for (int nt = 0; nt < 8; nt++) {
            const int col = warp_n * 64 + nt * 8 + (lane & 3) * 2;
            float v00 = C[mt][nt][0] + Cc[mt][nt][0] * CS + sbias[col];
            float v01 = C[mt][nt][1] + Cc[mt][nt][1] * CS + sbias[col + 1];
            float v10 = C[mt][nt][2] + Cc[mt][nt][2] * CS + sbias[col];
            float v11 = C[mt][nt][3] + Cc[mt][nt][3] * CS + sbias[col + 1];
            __nv_bfloat16 h00 = __float2bfloat16(v00), h01 = __float2bfloat16(v01);
            __nv_bfloat16 h10 = __float2bfloat16(v10), h11 = __float2bfloat16(v11);
            uint32_t hi0 = pack_bf16(v00, v01), hi1 = pack_bf16(v10, v11);
            uint32_t lo0 = pack_bf16(v00 - __bfloat162float(h00), v01 - __bfloat162float(h01));
            uint32_t lo1 = pack_bf16(v10 - __bfloat162float(h10), v11 - __bfloat162float(h11));
            size_t o0 = (size_t)row0 * 1024 + col0 + col;
            size_t o1 = (size_t)(row0 + 8) * 1024 + col0 + col;
            *(uint32_t*)&OutHi[o0] = hi0;  *(uint32_t*)&OutLo[o0] = lo0;
            *(uint32_t*)&OutHi[o1] = hi1;  *(uint32_t*)&OutLo[o1] = lo1;
        }
    }
}

// ---------------------------------------------------------------------------
// Tensor-core block-local attention; V consumed in [s][d] layout via
// ldmatrix.trans (no separate transpose kernel).
// smem: Qhi 8K | Qlo 8K | Khi 32K | Klo 32K | Vhi 32K | Vlo 32K = 144K.
// ---------------------------------------------------------------------------
#define SQ_HI   0
#define SQ_LO   8192
#define SK_HI   16384
#define SK_LO   49152
#define SV_HI   81920
#define SV_LO   114688
#define ATTN_SMEM 147456

__global__ __launch_bounds__(256) void attn_mma(
    const int* __restrict__ perm,
    float* __restrict__ out) {
    extern __shared__ __align__(128) char smem[];
    const uint32_t sb = smem_u32(smem);
    float* outbuf = (float*)smem;          // 64x64 fp32, overlays Q after logits
    __shared__ float smax[2][64];
    __shared__ float ssum[2][64];

    const int qt = blockIdx.x;
    const int g  = blockIdx.y;
    const int b  = blockIdx.z;
    const int blk = g >> 4, head = g & 15;
    const int src = perm[g];
    const int sblk = src >> 4, shead = src & 15;

    const int t = threadIdx.x, lane = t & 31, wid = t >> 5;
    const int warp_m = wid >> 1;
    const int warp_n = wid & 1;

    // ---- cp.async fills ----
    {
        const int qbase = b * 4096 + blk * 256 + qt * 64;
        for (int i = t; i < 512; i += 256) {
            int r = i >> 3, c = i & 7;
            uint32_t sw = (uint32_t)r * 128 + ((c ^ (r & 7)) * 16);
            size_t srcb = (size_t)(qbase + r) * 1024 + head * 64 + c * 8;
            CP_ASYNC16(sb + SQ_HI + sw, g_Ohi + srcb);
            CP_ASYNC16(sb + SQ_LO + sw, g_Olo + srcb);
        }
        const __nv_bfloat16* Kh = g_Ohi + (size_t)MH;
        const __nv_bfloat16* Kl = g_Olo + (size_t)MH;
        const __nv_bfloat16* Vh = g_Ohi + 2ull * MH;
        const __nv_bfloat16* Vl = g_Olo + 2ull * MH;
        const int kbase = b * 4096 + sblk * 256;
        for (int i = t; i < 2048; i += 256) {
            int r = i >> 3, c = i & 7;
            uint32_t sw = (uint32_t)r * 128 + ((c ^ (r & 7)) * 16);
            size_t srcb = (size_t)(kbase + r) * 1024 + shead * 64 + c * 8;
            CP_ASYNC16(sb + SK_HI + sw, Kh + srcb);
            CP_ASYNC16(sb + SK_LO + sw, Kl + srcb);
            CP_ASYNC16(sb + SV_HI + sw, Vh + srcb);
            CP_ASYNC16(sb + SV_LO + sw, Vl + srcb);
        }
    }
    CP_COMMIT();
    CP_WAIT0();
    __syncthreads();

    // ---- logits: S(16x128 per warp) = Q . K^T, 3-term bf16 ----
    float C[16][4];
    #pragma unroll
    for (int j = 0; j < 16; j++)
        #pragma unroll
        for (int k = 0; k < 4; k++) C[j][k] = 0.0f;

    const int a_r   = warp_m * 16 + (lane & 15);
    const uint32_t a_sw = (uint32_t)a_r * 128;
    const int b_r   = ((lane >> 4) << 3) + (lane & 7);
    const int b_csel = (lane >> 3) & 1;

    #pragma unroll
    for (int kt = 0; kt < 4; kt++) {
        uint32_t aQh[4], aQl[4];
        {
            int c = 2 * kt + (lane >> 4);
            uint32_t ra = sb + a_sw + ((c ^ (a_r & 7)) * 16);
            ldsm_x4(aQh, ra + SQ_HI);
            ldsm_x4(aQl, ra + SQ_LO);
        }
        uint32_t bKh[16][2], bKl[16][2];
        #pragma unroll
        for (int p = 0; p < 8; p++) {
            int row = warp_n * 128 + p * 16 + b_r;
            int c = 2 * kt + b_csel;
            uint32_t rb = sb + (uint32_t)row * 128 + ((c ^ (row & 7)) * 16);
            uint32_t rr[4];
            ldsm_x4(rr, rb + SK_HI);
            bKh[p * 2][0] = rr[0]; bKh[p * 2][1] = rr[1];
            bKh[p * 2 + 1][0] = rr[2]; bKh[p * 2 + 1][1] = rr[3];
            ldsm_x4(rr, rb + SK_LO);
            bKl[p * 2][0] = rr[0]; bKl[p * 2][1] = rr[1];
            bKl[p * 2 + 1][0] = rr[2]; bKl[p * 2 + 1][1] = rr[3];
        }
        #pragma unroll
        for (int nt = 0; nt < 16; nt++) {
            mma_bf16(C[nt], aQh, bKh[nt]);
            mma_bf16(C[nt], aQh, bKl[nt]);
            mma_bf16(C[nt], aQl, bKh[nt]);
        }
    }

    // ---- softmax on fragments ----
    const int fr = lane >> 2;
    const int gr0 = warp_m * 16 + fr;
    const int gr1 = gr0 + 8;

    float m0 = -1e30f, m1 = -1e30f;
    #pragma unroll
    for (int j = 0; j < 16; j++) {
        m0 = fmaxf(m0, fmaxf(C[j][0], C[j][1]));
        m1 = fmaxf(m1, fmaxf(C[j][2], C[j][3]));
    }
    m0 = fmaxf(m0, __shfl_xor_sync(0xffffffffu, m0, 1));
    m0 = fmaxf(m0, __shfl_xor_sync(0xffffffffu, m0, 2));
    m1 = fmaxf(m1, __shfl_xor_sync(0xffffffffu, m1, 1));
    m1 = fmaxf(m1, __shfl_xor_sync(0xffffffffu, m1, 2));
    if ((lane & 3) == 0) {
        smax[warp_n][gr0] = m0;
        smax[warp_n][gr1] = m1;
    }
    __syncthreads();
    m0 = fmaxf(smax[0][gr0], smax[1][gr0]);
    m1 = fmaxf(smax[0][gr1], smax[1][gr1]);

    float s0 = 0.0f, s1 = 0.0f;
    #pragma unroll
    for (int j = 0; j < 16; j++) {
        C[j][0] = fast_exp((C[j][0] - m0) * 0.125f);
        C[j][1] = fast_exp((C[j][1] - m0) * 0.125f);
        C[j][2] = fast_exp((C[j][2] - m1) * 0.125f);
        C[j][3] = fast_exp((C[j][3] - m1) * 0.125f);
        s0 += C[j][0] + C[j][1];
        s1 += C[j][2] + C[j][3];
    }
    s0 += __shfl_xor_sync(0xffffffffu, s0, 1);
    s0 += __shfl_xor_sync(0xffffffffu, s0, 2);
    s1 += __shfl_xor_sync(0xffffffffu, s1, 1);
    s1 += __shfl_xor_sync(0xffffffffu, s1, 2);
    if ((lane & 3) == 0) {
        ssum[warp_n][gr0] = s0;
        ssum[warp_n][gr1] = s1;
    }

    // ---- P -> bf16 hi/lo A-fragments in registers ----
    uint32_t aPh[8][4], aPl[8][4];
    #pragma unroll
    for (int kt = 0; kt < 8; kt++) {
        int j0 = 2 * kt, j1 = 2 * kt + 1;
        float v00 = C[j0][0], v01 = C[j0][1], v02 = C[j0][2], v03 = C[j0][3];
        float v10 = C[j1][0], v11 = C[j1][1], v12 = C[j1][2], v13 = C[j1][3];
        aPh[kt][0] = pack_bf16(v00, v01);
        aPh[kt][1] = pack_bf16(v02, v03);
        aPh[kt][2] = pack_bf16(v10, v11);
        aPh[kt][3] = pack_bf16(v12, v13);
        __nv_bfloat162 h;
        h = *(__nv_bfloat162*)&aPh[kt][0];
        aPl[kt][0] = pack_bf16(v00 - __bfloat162float(h.x), v01 - __bfloat162float(h.y));
        h = *(__nv_bfloat162*)&aPh[kt][1];
        aPl[kt][1] = pack_bf16(v02 - __bfloat162float(h.x), v03 - __bfloat162float(h.y));
        h = *(__nv_bfloat162*)&aPh[kt][2];
        aPl[kt][2] = pack_bf16(v10 - __bfloat162float(h.x), v11 - __bfloat162float(h.y));
        h = *(__nv_bfloat162*)&aPh[kt][3];
        aPl[kt][3] = pack_bf16(v12 - __bfloat162float(h.x), v13 - __bfloat162float(h.y));
    }

    // ---- AV: warp partial over its 128 k's; V via ldmatrix.trans ----
    float av[8][4];
    #pragma unroll
    for (int nt = 0; nt < 8; nt++)
        #pragma unroll
        for (int k = 0; k < 4; k++) av[nt][k] = 0.0f;

    #pragma unroll
    for (int kt = 0; kt < 8; kt++) {
        const int s0r = warp_n * 128 + kt * 16;
        uint32_t bVh[8][2], bVl[8][2];
        #pragma unroll
        for (int p = 0; p < 4; p++) {
            int row = s0r + (lane & 15);
            int c = 2 * p + (lane >> 4);
            uint32_t rb = sb + (uint32_t)row * 128 + ((c ^ (row & 7)) * 16);
            uint32_t rr[4];
            ldsm_x4_t(rr, rb + SV_HI);
            bVh[p * 2][0] = rr[0]; bVh[p * 2][1] = rr[1];
            bVh[p * 2 + 1][0] = rr[2]; bVh[p * 2 + 1][1] = rr[3];
            ldsm_x4_t(rr, rb + SV_LO);
            bVl[p * 2][0] = rr[0]; bVl[p * 2][1] = rr[1];
            bVl[p * 2 + 1][0] = rr[2]; bVl[p * 2 + 1][1] = rr[3];
        }
        #pragma unroll
        for (int nt = 0; nt < 8; nt++) {
            mma_bf16(av[nt], aPh[kt], bVh[nt]);
            mma_bf16(av[nt], aPh[kt], bVl[nt]);
            mma_bf16(av[nt], aPl[kt], bVh[nt]);
        }
    }

    // ---- combine warp_n pairs via smem overlay of Q ----
    __syncthreads();
    if (warp_n == 0) {
        #pragma unroll
        for (int nt = 0; nt < 8; nt++) {
            int col = nt * 8 + (lane & 3) * 2;
            outbuf[gr0 * 64 + col]     = av[nt][0];
            outbuf[gr0 * 64 + col + 1] = av[nt][1];
            outbuf[gr1 * 64 + col]     = av[nt][2];
            outbuf[gr1 * 64 + col + 1] = av[nt][3];
        }
    }
    __syncthreads();
    if (warp_n == 1) {
        #pragma unroll
        for (int nt = 0; nt < 8; nt++) {
            int col = nt * 8 + (lane & 3) * 2;
            outbuf[gr0 * 64 + col]     += av[nt][0];
            outbuf[gr0 * 64 + col + 1] += av[nt][1];
            outbuf[gr1 * 64 + col]     += av[nt][2];
            outbuf[gr1 * 64 + col + 1] += av[nt][3];
        }
    }
    __syncthreads();

    // ---- normalize by row sum and write ----
    const int obase = b * 4096 + blk * 256 + qt * 64;
    for (int i = t; i < 1024; i += 256) {
        int row = i >> 4, ch = i & 15;
        float inv = 1.0f / (ssum[0][row] + ssum[1][row]);
        float4 v = *(float4*)&outbuf[row * 64 + ch * 4];
        v.x *= inv; v.y *= inv; v.z *= inv; v.w *= inv;
        *(float4*)&out[((size_t)(obase + row) * 16 + head) * 64 + ch * 4] = v;
    }
}

// ---------------------------------------------------------------------------
extern "C" void kernel_launch(void* const* d_in, const int* in_sizes, int n_in,
                              void* d_out, int out_size) {
    const float* X    = (const float*)d_in[0];
    const int*   perm = (const int*)d_in[2];
    const float* Wq   = (const float*)d_in[3];
    const float* Bq   = (const float*)d_in[4];
    const float* Wk   = (const float*)d_in[5];
    const float* Bk   = (const float*)d_in[6];
    const float* Wv   = (const float*)d_in[7];
    const float* Bv   = (const float*)d_in[8];
    float* out        = (float*)d_out;
    (void)in_sizes; (void)n_in; (void)out_size;

    cudaFuncSetAttribute(qkv_gemm_mma, cudaFuncAttributeMaxDynamicSharedMemorySize, GEMM_SMEM);
    cudaFuncSetAttribute(attn_mma, cudaFuncAttributeMaxDynamicSharedMemorySize, ATTN_SMEM);

    cvt_x<<<MROWS * HIDDEN / 4 / 256, 256>>>(X);
    cvt_w<<<dim3(32, 32, 3), dim3(32, 8)>>>(Wq, Wk, Wv);

    qkv_gemm_mma<<<dim3(24, 64), 256, GEMM_SMEM>>>(Bq, Bk, Bv);

    attn_mma<<<dim3(4, 256, 2), 256, ATTN_SMEM>>>(perm, out);
}

// round 11
// speedup vs baseline: 1.7496x; 1.7496x over previous
#include <cuda_runtime.h>
#include <cuda_fp16.h>
#include <math.h>
#include <stdint.h>

// ---------------------------------------------------------------------------
// Problem constants
// ---------------------------------------------------------------------------
#define SEQ     4096
#define HIDDEN  1024
#define BATCH   2
#define MROWS   (BATCH * SEQ)   // 8192
#define MH      (MROWS * HIDDEN)

// GEMM operands (fp16)
__device__ __half g_X16[MH];                  // fp16(x)
__device__ __half g_Wh[3 * HIDDEN * HIDDEN];  // fp16(w), [proj*1024+n][k]
__device__ __half g_Wl[3 * HIDDEN * HIDDEN];  // fp16(w - fp16(w))
// Projection outputs, single fp16: [proj][m 8192][col 1024] (col = head*64+d)
__device__ __half g_O[3 * MH];

// ---------------------------------------------------------------------------
// PTX helpers
// ---------------------------------------------------------------------------
__device__ __forceinline__ uint32_t smem_u32(const void* p) {
    uint32_t a;
    asm("{ .reg .u64 t; cvta.to.shared.u64 t, %1; cvt.u32.u64 %0, t; }" : "=r"(a) : "l"(p));
    return a;
}
#define CP_ASYNC16(dst, src) \
    asm volatile("cp.async.cg.shared.global [%0], [%1], 16;" :: "r"(dst), "l"(src) : "memory")
#define CP_COMMIT() asm volatile("cp.async.commit_group;" ::: "memory")
#define CP_WAIT2()  asm volatile("cp.async.wait_group 2;" ::: "memory")
#define CP_WAIT1()  asm volatile("cp.async.wait_group 1;" ::: "memory")
#define CP_WAIT0()  asm volatile("cp.async.wait_group 0;" ::: "memory")

__device__ __forceinline__ void ldsm_x4(uint32_t* r, uint32_t addr) {
    asm volatile("ldmatrix.sync.aligned.m8n8.x4.shared.b16 {%0,%1,%2,%3}, [%4];"
                 : "=r"(r[0]), "=r"(r[1]), "=r"(r[2]), "=r"(r[3]) : "r"(addr));
}
__device__ __forceinline__ void ldsm_x4_t(uint32_t* r, uint32_t addr) {
    asm volatile("ldmatrix.sync.aligned.m8n8.x4.trans.shared.b16 {%0,%1,%2,%3}, [%4];"
                 : "=r"(r[0]), "=r"(r[1]), "=r"(r[2]), "=r"(r[3]) : "r"(addr));
}
__device__ __forceinline__ void mma_f16(float* c, const uint32_t* a, const uint32_t* b) {
    asm volatile("mma.sync.aligned.m16n8k16.row.col.f32.f16.f16.f32 "
                 "{%0,%1,%2,%3}, {%4,%5,%6,%7}, {%8,%9}, {%0,%1,%2,%3};"
                 : "+f"(c[0]), "+f"(c[1]), "+f"(c[2]), "+f"(c[3])
                 : "r"(a[0]), "r"(a[1]), "r"(a[2]), "r"(a[3]), "r"(b[0]), "r"(b[1]));
}
// Fast exp on the FMA pipe. |rel err| < 3e-6 for t in [-80, 0].
__device__ __forceinline__ float fast_exp(float t) {
    float y = t * 1.442695041f;
    float z = y + 12582912.0f;
    float n = z - 12582912.0f;
    float f = y - n;
    float p =            1.33336e-3f;
    p = fmaf(p, f,       9.61815e-3f);
    p = fmaf(p, f,       5.55042e-2f);
    p = fmaf(p, f,       2.40226e-1f);
    p = fmaf(p, f,       6.93147e-1f);
    p = fmaf(p, f,       1.0f);
    int e = __float2int_rn(n);
    float s = __int_as_float((e + 127) << 23);
    return s * p;
}
__device__ __forceinline__ uint32_t pack_h2(float a, float b) {
    __half2 h = __floats2half2_rn(a, b);
    return *(uint32_t*)&h;
}

// ---------------------------------------------------------------------------
// X -> fp16 (single)
// ---------------------------------------------------------------------------
__global__ __launch_bounds__(256) void cvt_x(const float* __restrict__ X) {
    int i = blockIdx.x * 256 + threadIdx.x;          // float4 index
    float4 v = ((const float4*)X)[i];
    ((uint32_t*)g_X16)[2 * i]     = pack_h2(v.x, v.y);
    ((uint32_t*)g_X16)[2 * i + 1] = pack_h2(v.z, v.w);
}

// ---------------------------------------------------------------------------
// W [k][n] fp32 -> [proj*1024+n][k]: fp16 hi + fp16 lo (transpose + split)
// ---------------------------------------------------------------------------
__global__ void cvt_w(const float* __restrict__ Wq,
                      const float* __restrict__ Wk,
                      const float* __restrict__ Wv) {
    __shared__ float s[32][33];
    const int proj = blockIdx.z;
    const float* W = proj == 0 ? Wq : (proj == 1 ? Wk : Wv);
    const int k0 = blockIdx.x * 32, n0 = blockIdx.y * 32;
    const int tx = threadIdx.x, ty = threadIdx.y;
    #pragma unroll
    for (int j = 0; j < 32; j += 8)
        s[ty + j][tx] = W[(k0 + ty + j) * 1024 + n0 + tx];
    __syncthreads();
    #pragma unroll
    for (int j = 0; j < 32; j += 8) {
        float v = s[tx][ty + j];
        int n = n0 + ty + j, k = k0 + tx;
        __half hi = __float2half_rn(v);
        __half lo = __float2half_rn(v - __half2float(hi));
        size_t o = ((size_t)proj * 1024 + n) * 1024 + k;
        g_Wh[o] = hi;
        g_Wl[o] = lo;
    }
}

// ---------------------------------------------------------------------------
// Projection GEMM, fp16 2-term: C = sum x16*(wh) + x16*(wl), fp32 accum.
// CTA 128x128, 8 warps (4m x 2n), K chunks of 32, 4-stage cp.async.
// smem rows: 32 halves (64B) at pitch 80B (conflict-free ldmatrix).
// ---------------------------------------------------------------------------
#define PITCHB   80
#define MATB     (128 * PITCHB)           // 10240
#define S_A      0
#define S_BH     10240
#define S_BL     20480
#define STAGE_BYTES 30720
#define NSTAGE   4
#define GEMM_SMEM (NSTAGE * STAGE_BYTES)  // 122880

__global__ __launch_bounds__(256) void qkv_gemm_mma(
    const float* __restrict__ Bq, const float* __restrict__ Bk,
    const float* __restrict__ Bv) {
    extern __shared__ __align__(128) char smem[];
    const uint32_t sb = smem_u32(smem);
    const int t = threadIdx.x, lane = t & 31, wid = t >> 5;
    const int warp_m = wid >> 1, warp_n = wid & 1;
    const int m0 = blockIdx.y * 128;
    const int n0g = blockIdx.x * 128;
    const int proj = n0g >> 10;
    const int col0 = n0g & 1023;
    const float* Bias = proj == 0 ? Bq : (proj == 1 ? Bk : Bv);
    __half* Out = g_O + (size_t)proj * MH;

    __shared__ float sbias[128];
    if (t < 128) sbias[t] = Bias[col0 + t];

    const int lrow = t >> 1;
    const __half* gA  = g_X16 + (size_t)(m0 + lrow) * 1024;
    const __half* gBh = g_Wh  + (size_t)(n0g + lrow) * 1024;
    const __half* gBl = g_Wl  + (size_t)(n0g + lrow) * 1024;

    auto load_chunk = [&](int slot, int kc) {
        uint32_t base = sb + slot * STAGE_BYTES + lrow * PITCHB;
        #pragma unroll
        for (int c2 = 0; c2 < 2; c2++) {
            int c = (t & 1) * 2 + c2;                // 16B chunk 0..3
            int go = kc + c * 8;
            CP_ASYNC16(base + S_A  + c * 16, gA  + go);
            CP_ASYNC16(base + S_BH + c * 16, gBh + go);
            CP_ASYNC16(base + S_BL + c * 16, gBl + go);
        }
    };

    float C[2][8][4];
    #pragma unroll
    for (int mt = 0; mt < 2; mt++)
        #pragma unroll
        for (int nt = 0; nt < 8; nt++)
            #pragma unroll
            for (int j = 0; j < 4; j++) C[mt][nt][j] = 0.0f;

    load_chunk(0, 0);  CP_COMMIT();
    load_chunk(1, 32); CP_COMMIT();
    load_chunk(2, 64); CP_COMMIT();

    const int a_r   = warp_m * 32 + (lane & 15);     // +mt*16
    const int b_r   = warp_n * 64 + ((lane >> 4) << 3) + (lane & 7);  // +p*16
    const int b_csel = (lane >> 3) & 1;

    for (int ch = 0; ch < 32; ch++) {
        if (ch <= 29)      CP_WAIT2();
        else if (ch == 30) CP_WAIT1();
        else               CP_WAIT0();
        __syncthreads();

        if (ch + 3 < 32) {
            load_chunk((ch + 3) & (NSTAGE - 1), (ch + 3) * 32);
            CP_COMMIT();
        }

        const uint32_t base = sb + (ch & (NSTAGE - 1)) * STAGE_BYTES;
        #pragma unroll
        for (int ks = 0; ks < 2; ks++) {
            uint32_t a[2][4];
            #pragma unroll
            for (int mt = 0; mt < 2; mt++) {
                uint32_t ra = base + S_A + (uint32_t)(a_r + mt * 16) * PITCHB
                            + (uint32_t)(lane >> 4) * 16 + ks * 32;
                ldsm_x4(a[mt], ra);
            }
            uint32_t bh[8][2], bl[8][2];
            #pragma unroll
            for (int p = 0; p < 4; p++) {
                uint32_t rb = base + (uint32_t)(b_r + p * 16) * PITCHB
                            + (uint32_t)b_csel * 16 + ks * 32;
                uint32_t rr[4];
                ldsm_x4(rr, rb + S_BH);
                bh[p * 2][0] = rr[0]; bh[p * 2][1] = rr[1];
                bh[p * 2 + 1][0] = rr[2]; bh[p * 2 + 1][1] = rr[3];
                ldsm_x4(rr, rb + S_BL);
                bl[p * 2][0] = rr[0]; bl[p * 2][1] = rr[1];
                bl[p * 2 + 1][0] = rr[2]; bl[p * 2 + 1][1] = rr[3];
            }
            #pragma unroll
            for (int mt = 0; mt < 2; mt++)
                #pragma unroll
                for (int nt = 0; nt < 8; nt++) {
                    mma_f16(C[mt][nt], a[mt], bh[nt]);
                    mma_f16(C[mt][nt], a[mt], bl[nt]);
                }
        }
    }

    // epilogue: bias, convert to fp16, 4B stores
    #pragma unroll
    for (int mt = 0; mt < 2; mt++) {
        const int row0 = m0 + warp_m * 32 + mt * 16 + (lane >> 2);
        #pragma unroll
        for (int nt = 0; nt < 8; nt++) {
            const int col = warp_n * 64 + nt * 8 + (lane & 3) * 2;
            uint32_t o0 = pack_h2(C[mt][nt][0] + sbias[col],
                                  C[mt][nt][1] + sbias[col + 1]);
            uint32_t o1 = pack_h2(C[mt][nt][2] + sbias[col],
                                  C[mt][nt][3] + sbias[col + 1]);
            *(uint32_t*)&Out[(size_t)row0 * 1024 + col0 + col] = o0;
            *(uint32_t*)&Out[(size_t)(row0 + 8) * 1024 + col0 + col] = o1;
        }
    }
}

// ---------------------------------------------------------------------------
// Tensor-core block-local attention, fp16 single-precision operands.
// CTA = (64-row q tile, group g, batch b), 8 warps (4m x 2n).
// smem: Q 8K | K 32K | V 32K = 72K -> 3 CTAs/SM.
// QK 1-term, P single fp16, AV 1-term (V via ldmatrix.trans).
// ---------------------------------------------------------------------------
#define SQ      0
#define SK      8192
#define SV      40960
#define ATTN_SMEM 73728

__global__ __launch_bounds__(256) void attn_mma(
    const int* __restrict__ perm,
    float* __restrict__ out) {
    extern __shared__ __align__(128) char smem[];
    const uint32_t sb = smem_u32(smem);
    float* outbuf = (float*)smem;          // 64x64 fp32, overlays Q+K after use
    __shared__ float smax[2][64];
    __shared__ float ssum[2][64];

    const int qt = blockIdx.x;
    const int g  = blockIdx.y;
    const int b  = blockIdx.z;
    const int blk = g >> 4, head = g & 15;
    const int src = perm[g];
    const int sblk = src >> 4, shead = src & 15;

    const int t = threadIdx.x, lane = t & 31, wid = t >> 5;
    const int warp_m = wid >> 1;
    const int warp_n = wid & 1;

    // ---- cp.async fills ----
    {
        const int qbase = b * 4096 + blk * 256 + qt * 64;
        for (int i = t; i < 512; i += 256) {
            int r = i >> 3, c = i & 7;
            uint32_t sw = (uint32_t)r * 128 + ((c ^ (r & 7)) * 16);
            CP_ASYNC16(sb + SQ + sw, g_O + (size_t)(qbase + r) * 1024 + head * 64 + c * 8);
        }
        const __half* K = g_O + (size_t)MH;
        const __half* V = g_O + 2ull * MH;
        const int kbase = b * 4096 + sblk * 256;
        for (int i = t; i < 2048; i += 256) {
            int r = i >> 3, c = i & 7;
            uint32_t sw = (uint32_t)r * 128 + ((c ^ (r & 7)) * 16);
            size_t srcb = (size_t)(kbase + r) * 1024 + shead * 64 + c * 8;
            CP_ASYNC16(sb + SK + sw, K + srcb);
            CP_ASYNC16(sb + SV + sw, V + srcb);
        }
    }
    CP_COMMIT();
    CP_WAIT0();
    __syncthreads();

    // ---- logits: S(16x128 per warp) = Q . K^T, 1-term fp16 ----
    float C[16][4];
    #pragma unroll
    for (int j = 0; j < 16; j++)
        #pragma unroll
        for (int k = 0; k < 4; k++) C[j][k] = 0.0f;

    const int a_r   = warp_m * 16 + (lane & 15);
    const uint32_t a_sw = (uint32_t)a_r * 128;
    const int b_r   = ((lane >> 4) << 3) + (lane & 7);
    const int b_csel = (lane >> 3) & 1;

    #pragma unroll
    for (int kt = 0; kt < 4; kt++) {
        uint32_t aQ[4];
        {
            int c = 2 * kt + (lane >> 4);
            ldsm_x4(aQ, sb + SQ + a_sw + ((c ^ (a_r & 7)) * 16));
        }
        uint32_t bK[16][2];
        #pragma unroll
        for (int p = 0; p < 8; p++) {
            int row = warp_n * 128 + p * 16 + b_r;
            int c = 2 * kt + b_csel;
            uint32_t rr[4];
            ldsm_x4(rr, sb + SK + (uint32_t)row * 128 + ((c ^ (row & 7)) * 16));
            bK[p * 2][0] = rr[0]; bK[p * 2][1] = rr[1];
            bK[p * 2 + 1][0] = rr[2]; bK[p * 2 + 1][1] = rr[3];
        }
        #pragma unroll
        for (int nt = 0; nt < 16; nt++)
            mma_f16(C[nt], aQ, bK[nt]);
    }

    // ---- softmax on fragments ----
    const int fr = lane >> 2;
    const int gr0 = warp_m * 16 + fr;
    const int gr1 = gr0 + 8;

    float m0 = -1e30f, m1 = -1e30f;
    #pragma unroll
    for (int j = 0; j < 16; j++) {
        m0 = fmaxf(m0, fmaxf(C[j][0], C[j][1]));
        m1 = fmaxf(m1, fmaxf(C[j][2], C[j][3]));
    }
    m0 = fmaxf(m0, __shfl_xor_sync(0xffffffffu, m0, 1));
    m0 = fmaxf(m0, __shfl_xor_sync(0xffffffffu, m0, 2));
    m1 = fmaxf(m1, __shfl_xor_sync(0xffffffffu, m1, 1));
    m1 = fmaxf(m1, __shfl_xor_sync(0xffffffffu, m1, 2));
    if ((lane & 3) == 0) {
        smax[warp_n][gr0] = m0;
        smax[warp_n][gr1] = m1;
    }
    __syncthreads();
    m0 = fmaxf(smax[0][gr0], smax[1][gr0]);
    m1 = fmaxf(smax[0][gr1], smax[1][gr1]);

    float s0 = 0.0f, s1 = 0.0f;
    #pragma unroll
    for (int j = 0; j < 16; j++) {
        C[j][0] = fast_exp((C[j][0] - m0) * 0.125f);
        C[j][1] = fast_exp((C[j][1] - m0) * 0.125f);
        C[j][2] = fast_exp((C[j][2] - m1) * 0.125f);
        C[j][3] = fast_exp((C[j][3] - m1) * 0.125f);
        s0 += C[j][0] + C[j][1];
        s1 += C[j][2] + C[j][3];
    }
    s0 += __shfl_xor_sync(0xffffffffu, s0, 1);
    s0 += __shfl_xor_sync(0xffffffffu, s0, 2);
    s1 += __shfl_xor_sync(0xffffffffu, s1, 1);
    s1 += __shfl_xor_sync(0xffffffffu, s1, 2);
    if ((lane & 3) == 0) {
        ssum[warp_n][gr0] = s0;
        ssum[warp_n][gr1] = s1;
    }

    // ---- P (unnormalized) -> fp16 A-fragments in registers ----
    uint32_t aP[8][4];
    #pragma unroll
    for (int kt = 0; kt < 8; kt++) {
        int j0 = 2 * kt, j1 = 2 * kt + 1;
        aP[kt][0] = pack_h2(C[j0][0], C[j0][1]);
        aP[kt][1] = pack_h2(C[j0][2], C[j0][3]);
        aP[kt][2] = pack_h2(C[j1][0], C[j1][1]);
        aP[kt][3] = pack_h2(C[j1][2], C[j1][3]);
    }

    // ---- AV: warp partial over its 128 k's; V via ldmatrix.trans ----
    float av[8][4];
    #pragma unroll
    for (int nt = 0; nt < 8; nt++)
        #pragma unroll
        for (int k = 0; k < 4; k++) av[nt][k] = 0.0f;

    #pragma unroll
    for (int kt = 0; kt < 8; kt++) {
        const int s0r = warp_n * 128 + kt * 16;
        uint32_t bV[8][2];
        #pragma unroll
        for (int p = 0; p < 4; p++) {
            int row = s0r + (lane & 15);
            int c = 2 * p + (lane >> 4);
            uint32_t rr[4];
            ldsm_x4_t(rr, sb + SV + (uint32_t)row * 128 + ((c ^ (row & 7)) * 16));
            bV[p * 2][0] = rr[0]; bV[p * 2][1] = rr[1];
            bV[p * 2 + 1][0] = rr[2]; bV[p * 2 + 1][1] = rr[3];
        }
        #pragma unroll
        for (int nt = 0; nt < 8; nt++)
            mma_f16(av[nt], aP[kt], bV[nt]);
    }

    // ---- combine warp_n pairs via smem overlay ----
    __syncthreads();
    if (warp_n == 0) {
        #pragma unroll
        for (int nt = 0; nt < 8; nt++) {
            int col = nt * 8 + (lane & 3) * 2;
            outbuf[gr0 * 64 + col]     = av[nt][0];
            outbuf[gr0 * 64 + col + 1] = av[nt][1];
            outbuf[gr1 * 64 + col]     = av[nt][2];
            outbuf[gr1 * 64 + col + 1] = av[nt][3];
        }
    }
    __syncthreads();
    if (warp_n == 1) {
        #pragma unroll
        for (int nt = 0; nt < 8; nt++) {
            int col = nt * 8 + (lane & 3) * 2;
            outbuf[gr0 * 64 + col]     += av[nt][0];
            outbuf[gr0 * 64 + col + 1] += av[nt][1];
            outbuf[gr1 * 64 + col]     += av[nt][2];
            outbuf[gr1 * 64 + col + 1] += av[nt][3];
        }
    }
    __syncthreads();

    // ---- normalize by row sum and write ----
    const int obase = b * 4096 + blk * 256 + qt * 64;
    for (int i = t; i < 1024; i += 256) {
        int row = i >> 4, ch = i & 15;
        float inv = 1.0f / (ssum[0][row] + ssum[1][row]);
        float4 v = *(float4*)&outbuf[row * 64 + ch * 4];
        v.x *= inv; v.y *= inv; v.z *= inv; v.w *= inv;
        *(float4*)&out[((size_t)(obase + row) * 16 + head) * 64 + ch * 4] = v;
    }
}

// ---------------------------------------------------------------------------
extern "C" void kernel_launch(void* const* d_in, const int* in_sizes, int n_in,
                              void* d_out, int out_size) {
    const float* X    = (const float*)d_in[0];
    const int*   perm = (const int*)d_in[2];
    const float* Wq   = (const float*)d_in[3];
    const float* Bq   = (const float*)d_in[4];
    const float* Wk   = (const float*)d_in[5];
    const float* Bk   = (const float*)d_in[6];
    const float* Wv   = (const float*)d_in[7];
    const float* Bv   = (const float*)d_in[8];
    float* out        = (float*)d_out;
    (void)in_sizes; (void)n_in; (void)out_size;

    cudaFuncSetAttribute(qkv_gemm_mma, cudaFuncAttributeMaxDynamicSharedMemorySize, GEMM_SMEM);
    cudaFuncSetAttribute(attn_mma, cudaFuncAttributeMaxDynamicSharedMemorySize, ATTN_SMEM);

    cvt_x<<<MROWS * HIDDEN / 4 / 256, 256>>>(X);
    cvt_w<<<dim3(32, 32, 3), dim3(32, 8)>>>(Wq, Wk, Wv);

    qkv_gemm_mma<<<dim3(24, 64), 256, GEMM_SMEM>>>(Bq, Bk, Bv);

    attn_mma<<<dim3(4, 256, 2), 256, ATTN_SMEM>>>(perm, out);
}

// round 12
// speedup vs baseline: 2.9184x; 1.6680x over previous
#include <cuda_runtime.h>
#include <cuda_fp16.h>
#include <math.h>
#include <stdint.h>

// ---------------------------------------------------------------------------
// Problem constants
// ---------------------------------------------------------------------------
#define SEQ     4096
#define HIDDEN  1024
#define BATCH   2
#define MROWS   (BATCH * SEQ)   // 8192
#define MH      (MROWS * HIDDEN)

// GEMM operands (fp16, single precision each)
__device__ __half g_X16[MH];                  // fp16(x)
__device__ __half g_Wh[3 * HIDDEN * HIDDEN];  // fp16(w), [proj*1024+n][k]
// Projection outputs, single fp16: [proj][m 8192][col 1024] (col = head*64+d)
__device__ __half g_O[3 * MH];

// ---------------------------------------------------------------------------
// PTX helpers
// ---------------------------------------------------------------------------
__device__ __forceinline__ uint32_t smem_u32(const void* p) {
    uint32_t a;
    asm("{ .reg .u64 t; cvta.to.shared.u64 t, %1; cvt.u32.u64 %0, t; }" : "=r"(a) : "l"(p));
    return a;
}
#define CP_ASYNC16(dst, src) \
    asm volatile("cp.async.cg.shared.global [%0], [%1], 16;" :: "r"(dst), "l"(src) : "memory")
#define CP_COMMIT() asm volatile("cp.async.commit_group;" ::: "memory")
#define CP_WAIT2()  asm volatile("cp.async.wait_group 2;" ::: "memory")
#define CP_WAIT1()  asm volatile("cp.async.wait_group 1;" ::: "memory")
#define CP_WAIT0()  asm volatile("cp.async.wait_group 0;" ::: "memory")

__device__ __forceinline__ void ldsm_x4(uint32_t* r, uint32_t addr) {
    asm volatile("ldmatrix.sync.aligned.m8n8.x4.shared.b16 {%0,%1,%2,%3}, [%4];"
                 : "=r"(r[0]), "=r"(r[1]), "=r"(r[2]), "=r"(r[3]) : "r"(addr));
}
__device__ __forceinline__ void ldsm_x4_t(uint32_t* r, uint32_t addr) {
    asm volatile("ldmatrix.sync.aligned.m8n8.x4.trans.shared.b16 {%0,%1,%2,%3}, [%4];"
                 : "=r"(r[0]), "=r"(r[1]), "=r"(r[2]), "=r"(r[3]) : "r"(addr));
}
__device__ __forceinline__ void mma_f16(float* c, const uint32_t* a, const uint32_t* b) {
    asm volatile("mma.sync.aligned.m16n8k16.row.col.f32.f16.f16.f32 "
                 "{%0,%1,%2,%3}, {%4,%5,%6,%7}, {%8,%9}, {%0,%1,%2,%3};"
                 : "+f"(c[0]), "+f"(c[1]), "+f"(c[2]), "+f"(c[3])
                 : "r"(a[0]), "r"(a[1]), "r"(a[2]), "r"(a[3]), "r"(b[0]), "r"(b[1]));
}
// Fast exp on the FMA pipe. |rel err| < 3e-6 for t in [-80, 0].
__device__ __forceinline__ float fast_exp(float t) {
    float y = t * 1.442695041f;
    float z = y + 12582912.0f;
    float n = z - 12582912.0f;
    float f = y - n;
    float p =            1.33336e-3f;
    p = fmaf(p, f,       9.61815e-3f);
    p = fmaf(p, f,       5.55042e-2f);
    p = fmaf(p, f,       2.40226e-1f);
    p = fmaf(p, f,       6.93147e-1f);
    p = fmaf(p, f,       1.0f);
    int e = __float2int_rn(n);
    float s = __int_as_float((e + 127) << 23);
    return s * p;
}
__device__ __forceinline__ uint32_t pack_h2(float a, float b) {
    __half2 h = __floats2half2_rn(a, b);
    return *(uint32_t*)&h;
}

// ---------------------------------------------------------------------------
// X -> fp16
// ---------------------------------------------------------------------------
__global__ __launch_bounds__(256) void cvt_x(const float* __restrict__ X) {
    int i = blockIdx.x * 256 + threadIdx.x;          // float4 index
    float4 v = ((const float4*)X)[i];
    ((uint32_t*)g_X16)[2 * i]     = pack_h2(v.x, v.y);
    ((uint32_t*)g_X16)[2 * i + 1] = pack_h2(v.z, v.w);
}

// ---------------------------------------------------------------------------
// W [k][n] fp32 -> [proj*1024+n][k] fp16 (transpose)
// ---------------------------------------------------------------------------
__global__ void cvt_w(const float* __restrict__ Wq,
                      const float* __restrict__ Wk,
                      const float* __restrict__ Wv) {
    __shared__ float s[32][33];
    const int proj = blockIdx.z;
    const float* W = proj == 0 ? Wq : (proj == 1 ? Wk : Wv);
    const int k0 = blockIdx.x * 32, n0 = blockIdx.y * 32;
    const int tx = threadIdx.x, ty = threadIdx.y;
    #pragma unroll
    for (int j = 0; j < 32; j += 8)
        s[ty + j][tx] = W[(k0 + ty + j) * 1024 + n0 + tx];
    __syncthreads();
    #pragma unroll
    for (int j = 0; j < 32; j += 8) {
        float v = s[tx][ty + j];
        int n = n0 + ty + j, k = k0 + tx;
        g_Wh[((size_t)proj * 1024 + n) * 1024 + k] = __float2half_rn(v);
    }
}

// ---------------------------------------------------------------------------
// Projection GEMM, fp16 1-term: C = sum x16*w16, fp32 accum.
// CTA 128x128, 8 warps (4m x 2n), K chunks of 32, 4-stage cp.async.
// smem rows: 32 halves (64B) at pitch 80B (conflict-free ldmatrix).
// ---------------------------------------------------------------------------
#define PITCHB   80
#define MATB     (128 * PITCHB)           // 10240
#define S_A      0
#define S_BH     10240
#define STAGE_BYTES 20480
#define NSTAGE   4
#define GEMM_SMEM (NSTAGE * STAGE_BYTES)  // 81920

__global__ __launch_bounds__(256) void qkv_gemm_mma(
    const float* __restrict__ Bq, const float* __restrict__ Bk,
    const float* __restrict__ Bv) {
    extern __shared__ __align__(128) char smem[];
    const uint32_t sb = smem_u32(smem);
    const int t = threadIdx.x, lane = t & 31, wid = t >> 5;
    const int warp_m = wid >> 1, warp_n = wid & 1;
    const int m0 = blockIdx.y * 128;
    const int n0g = blockIdx.x * 128;
    const int proj = n0g >> 10;
    const int col0 = n0g & 1023;
    const float* Bias = proj == 0 ? Bq : (proj == 1 ? Bk : Bv);
    __half* Out = g_O + (size_t)proj * MH;

    __shared__ float sbias[128];
    if (t < 128) sbias[t] = Bias[col0 + t];

    const int lrow = t >> 1;
    const __half* gA  = g_X16 + (size_t)(m0 + lrow) * 1024;
    const __half* gBh = g_Wh  + (size_t)(n0g + lrow) * 1024;

    auto load_chunk = [&](int slot, int kc) {
        uint32_t base = sb + slot * STAGE_BYTES + lrow * PITCHB;
        #pragma unroll
        for (int c2 = 0; c2 < 2; c2++) {
            int c = (t & 1) * 2 + c2;                // 16B chunk 0..3
            int go = kc + c * 8;
            CP_ASYNC16(base + S_A  + c * 16, gA  + go);
            CP_ASYNC16(base + S_BH + c * 16, gBh + go);
        }
    };

    float C[2][8][4];
    #pragma unroll
    for (int mt = 0; mt < 2; mt++)
        #pragma unroll
        for (int nt = 0; nt < 8; nt++)
            #pragma unroll
            for (int j = 0; j < 4; j++) C[mt][nt][j] = 0.0f;

    load_chunk(0, 0);  CP_COMMIT();
    load_chunk(1, 32); CP_COMMIT();
    load_chunk(2, 64); CP_COMMIT();

    const int a_r   = warp_m * 32 + (lane & 15);     // +mt*16
    const int b_r   = warp_n * 64 + ((lane >> 4) << 3) + (lane & 7);  // +p*16
    const int b_csel = (lane >> 3) & 1;

    for (int ch = 0; ch < 32; ch++) {
        if (ch <= 29)      CP_WAIT2();
        else if (ch == 30) CP_WAIT1();
        else               CP_WAIT0();
        __syncthreads();

        if (ch + 3 < 32) {
            load_chunk((ch + 3) & (NSTAGE - 1), (ch + 3) * 32);
            CP_COMMIT();
        }

        const uint32_t base = sb + (ch & (NSTAGE - 1)) * STAGE_BYTES;
        #pragma unroll
        for (int ks = 0; ks < 2; ks++) {
            uint32_t a[2][4];
            #pragma unroll
            for (int mt = 0; mt < 2; mt++) {
                uint32_t ra = base + S_A + (uint32_t)(a_r + mt * 16) * PITCHB
                            + (uint32_t)(lane >> 4) * 16 + ks * 32;
                ldsm_x4(a[mt], ra);
            }
            uint32_t bh[8][2];
            #pragma unroll
            for (int p = 0; p < 4; p++) {
                uint32_t rb = base + S_BH + (uint32_t)(b_r + p * 16) * PITCHB
                            + (uint32_t)b_csel * 16 + ks * 32;
                uint32_t rr[4];
                ldsm_x4(rr, rb);
                bh[p * 2][0] = rr[0]; bh[p * 2][1] = rr[1];
                bh[p * 2 + 1][0] = rr[2]; bh[p * 2 + 1][1] = rr[3];
            }
            #pragma unroll
            for (int mt = 0; mt < 2; mt++)
                #pragma unroll
                for (int nt = 0; nt < 8; nt++)
                    mma_f16(C[mt][nt], a[mt], bh[nt]);
        }
    }

    // epilogue: bias, convert to fp16, 4B stores
    #pragma unroll
    for (int mt = 0; mt < 2; mt++) {
        const int row0 = m0 + warp_m * 32 + mt * 16 + (lane >> 2);
        #pragma unroll
        for (int nt = 0; nt < 8; nt++) {
            const int col = warp_n * 64 + nt * 8 + (lane & 3) * 2;
            uint32_t o0 = pack_h2(C[mt][nt][0] + sbias[col],
                                  C[mt][nt][1] + sbias[col + 1]);
            uint32_t o1 = pack_h2(C[mt][nt][2] + sbias[col],
                                  C[mt][nt][3] + sbias[col + 1]);
            *(uint32_t*)&Out[(size_t)row0 * 1024 + col0 + col] = o0;
            *(uint32_t*)&Out[(size_t)(row0 + 8) * 1024 + col0 + col] = o1;
        }
    }
}

// ---------------------------------------------------------------------------
// Tensor-core block-local attention, fp16 single-precision operands.
// CTA = (64-row q tile, group g, batch b), 8 warps (4m x 2n).
// smem: Q 8K | K 32K | V 32K = 72K -> 3 CTAs/SM.
// ---------------------------------------------------------------------------
#define SQ      0
#define SK      8192
#define SV      40960
#define ATTN_SMEM 73728

__global__ __launch_bounds__(256) void attn_mma(
    const int* __restrict__ perm,
    float* __restrict__ out) {
    extern __shared__ __align__(128) char smem[];
    const uint32_t sb = smem_u32(smem);
    float* outbuf = (float*)smem;          // 64x64 fp32, overlays Q+K after use
    __shared__ float smax[2][64];
    __shared__ float ssum[2][64];

    const int qt = blockIdx.x;
    const int g  = blockIdx.y;
    const int b  = blockIdx.z;
    const int blk = g >> 4, head = g & 15;
    const int src = perm[g];
    const int sblk = src >> 4, shead = src & 15;

    const int t = threadIdx.x, lane = t & 31, wid = t >> 5;
    const int warp_m = wid >> 1;
    const int warp_n = wid & 1;

    // ---- cp.async fills ----
    {
        const int qbase = b * 4096 + blk * 256 + qt * 64;
        for (int i = t; i < 512; i += 256) {
            int r = i >> 3, c = i & 7;
            uint32_t sw = (uint32_t)r * 128 + ((c ^ (r & 7)) * 16);
            CP_ASYNC16(sb + SQ + sw, g_O + (size_t)(qbase + r) * 1024 + head * 64 + c * 8);
        }
        const __half* K = g_O + (size_t)MH;
        const __half* V = g_O + 2ull * MH;
        const int kbase = b * 4096 + sblk * 256;
        for (int i = t; i < 2048; i += 256) {
            int r = i >> 3, c = i & 7;
            uint32_t sw = (uint32_t)r * 128 + ((c ^ (r & 7)) * 16);
            size_t srcb = (size_t)(kbase + r) * 1024 + shead * 64 + c * 8;
            CP_ASYNC16(sb + SK + sw, K + srcb);
            CP_ASYNC16(sb + SV + sw, V + srcb);
        }
    }
    CP_COMMIT();
    CP_WAIT0();
    __syncthreads();

    // ---- logits: S(16x128 per warp) = Q . K^T ----
    float C[16][4];
    #pragma unroll
    for (int j = 0; j < 16; j++)
        #pragma unroll
        for (int k = 0; k < 4; k++) C[j][k] = 0.0f;

    const int a_r   = warp_m * 16 + (lane & 15);
    const uint32_t a_sw = (uint32_t)a_r * 128;
    const int b_r   = ((lane >> 4) << 3) + (lane & 7);
    const int b_csel = (lane >> 3) & 1;

    #pragma unroll
    for (int kt = 0; kt < 4; kt++) {
        uint32_t aQ[4];
        {
            int c = 2 * kt + (lane >> 4);
            ldsm_x4(aQ, sb + SQ + a_sw + ((c ^ (a_r & 7)) * 16));
        }
        uint32_t bK[16][2];
        #pragma unroll
        for (int p = 0; p < 8; p++) {
            int row = warp_n * 128 + p * 16 + b_r;
            int c = 2 * kt + b_csel;
            uint32_t rr[4];
            ldsm_x4(rr, sb + SK + (uint32_t)row * 128 + ((c ^ (row & 7)) * 16));
            bK[p * 2][0] = rr[0]; bK[p * 2][1] = rr[1];
            bK[p * 2 + 1][0] = rr[2]; bK[p * 2 + 1][1] = rr[3];
        }
        #pragma unroll
        for (int nt = 0; nt < 16; nt++)
            mma_f16(C[nt], aQ, bK[nt]);
    }

    // ---- softmax on fragments ----
    const int fr = lane >> 2;
    const int gr0 = warp_m * 16 + fr;
    const int gr1 = gr0 + 8;

    float m0 = -1e30f, m1 = -1e30f;
    #pragma unroll
    for (int j = 0; j < 16; j++) {
        m0 = fmaxf(m0, fmaxf(C[j][0], C[j][1]));
        m1 = fmaxf(m1, fmaxf(C[j][2], C[j][3]));
    }
    m0 = fmaxf(m0, __shfl_xor_sync(0xffffffffu, m0, 1));
    m0 = fmaxf(m0, __shfl_xor_sync(0xffffffffu, m0, 2));
    m1 = fmaxf(m1, __shfl_xor_sync(0xffffffffu, m1, 1));
    m1 = fmaxf(m1, __shfl_xor_sync(0xffffffffu, m1, 2));
    if ((lane & 3) == 0) {
        smax[warp_n][gr0] = m0;
        smax[warp_n][gr1] = m1;
    }
    __syncthreads();
    m0 = fmaxf(smax[0][gr0], smax[1][gr0]);
    m1 = fmaxf(smax[0][gr1], smax[1][gr1]);

    float s0 = 0.0f, s1 = 0.0f;
    #pragma unroll
    for (int j = 0; j < 16; j++) {
        C[j][0] = fast_exp((C[j][0] - m0) * 0.125f);
        C[j][1] = fast_exp((C[j][1] - m0) * 0.125f);
        C[j][2] = fast_exp((C[j][2] - m1) * 0.125f);
        C[j][3] = fast_exp((C[j][3] - m1) * 0.125f);
        s0 += C[j][0] + C[j][1];
        s1 += C[j][2] + C[j][3];
    }
    s0 += __shfl_xor_sync(0xffffffffu, s0, 1);
    s0 += __shfl_xor_sync(0xffffffffu, s0, 2);
    s1 += __shfl_xor_sync(0xffffffffu, s1, 1);
    s1 += __shfl_xor_sync(0xffffffffu, s1, 2);
    if ((lane & 3) == 0) {
        ssum[warp_n][gr0] = s0;
        ssum[warp_n][gr1] = s1;
    }

    // ---- P (unnormalized) -> fp16 A-fragments in registers ----
    uint32_t aP[8][4];
    #pragma unroll
    for (int kt = 0; kt < 8; kt++) {
        int j0 = 2 * kt, j1 = 2 * kt + 1;
        aP[kt][0] = pack_h2(C[j0][0], C[j0][1]);
        aP[kt][1] = pack_h2(C[j0][2], C[j0][3]);
        aP[kt][2] = pack_h2(C[j1][0], C[j1][1]);
        aP[kt][3] = pack_h2(C[j1][2], C[j1][3]);
    }

    // ---- AV: warp partial over its 128 k's; V via ldmatrix.trans ----
    float av[8][4];
    #pragma unroll
    for (int nt = 0; nt < 8; nt++)
        #pragma unroll
        for (int k = 0; k < 4; k++) av[nt][k] = 0.0f;

    #pragma unroll
    for (int kt = 0; kt < 8; kt++) {
        const int s0r = warp_n * 128 + kt * 16;
        uint32_t bV[8][2];
        #pragma unroll
        for (int p = 0; p < 4; p++) {
            int row = s0r + (lane & 15);
            int c = 2 * p + (lane >> 4);
            uint32_t rr[4];
            ldsm_x4_t(rr, sb + SV + (uint32_t)row * 128 + ((c ^ (row & 7)) * 16));
            bV[p * 2][0] = rr[0]; bV[p * 2][1] = rr[1];
            bV[p * 2 + 1][0] = rr[2]; bV[p * 2 + 1][1] = rr[3];
        }
        #pragma unroll
        for (int nt = 0; nt < 8; nt++)
            mma_f16(av[nt], aP[kt], bV[nt]);
    }

    // ---- combine warp_n pairs via smem overlay ----
    __syncthreads();
    if (warp_n == 0) {
        #pragma unroll
        for (int nt = 0; nt < 8; nt++) {
            int col = nt * 8 + (lane & 3) * 2;
            outbuf[gr0 * 64 + col]     = av[nt][0];
            outbuf[gr0 * 64 + col + 1] = av[nt][1];
            outbuf[gr1 * 64 + col]     = av[nt][2];
            outbuf[gr1 * 64 + col + 1] = av[nt][3];
        }
    }
    __syncthreads();
    if (warp_n == 1) {
        #pragma unroll
        for (int nt = 0; nt < 8; nt++) {
            int col = nt * 8 + (lane & 3) * 2;
            outbuf[gr0 * 64 + col]     += av[nt][0];
            outbuf[gr0 * 64 + col + 1] += av[nt][1];
            outbuf[gr1 * 64 + col]     += av[nt][2];
            outbuf[gr1 * 64 + col + 1] += av[nt][3];
        }
    }
    __syncthreads();

    // ---- normalize by row sum and write ----
    const int obase = b * 4096 + blk * 256 + qt * 64;
    for (int i = t; i < 1024; i += 256) {
        int row = i >> 4, ch = i & 15;
        float inv = 1.0f / (ssum[0][row] + ssum[1][row]);
        float4 v = *(float4*)&outbuf[row * 64 + ch * 4];
        v.x *= inv; v.y *= inv; v.z *= inv; v.w *= inv;
        *(float4*)&out[((size_t)(obase + row) * 16 + head) * 64 + ch * 4] = v;
    }
}

// ---------------------------------------------------------------------------
extern "C" void kernel_launch(void* const* d_in, const int* in_sizes, int n_in,
                              void* d_out, int out_size) {
    const float* X    = (const float*)d_in[0];
    const int*   perm = (const int*)d_in[2];
    const float* Wq   = (const float*)d_in[3];
    const float* Bq   = (const float*)d_in[4];
    const float* Wk   = (const float*)d_in[5];
    const float* Bk   = (const float*)d_in[6];
    const float* Wv   = (const float*)d_in[7];
    const float* Bv   = (const float*)d_in[8];
    float* out        = (float*)d_out;
    (void)in_sizes; (void)n_in; (void)out_size;

    cudaFuncSetAttribute(qkv_gemm_mma, cudaFuncAttributeMaxDynamicSharedMemorySize, GEMM_SMEM);
    cudaFuncSetAttribute(attn_mma, cudaFuncAttributeMaxDynamicSharedMemorySize, ATTN_SMEM);

    cvt_x<<<MROWS * HIDDEN / 4 / 256, 256>>>(X);
    cvt_w<<<dim3(32, 32, 3), dim3(32, 8)>>>(Wq, Wk, Wv);

    qkv_gemm_mma<<<dim3(24, 64), 256, GEMM_SMEM>>>(Bq, Bk, Bv);

    attn_mma<<<dim3(4, 256, 2), 256, ATTN_SMEM>>>(perm, out);
}